// round 12
// baseline (speedup 1.0000x reference)
#include <cuda_runtime.h>
#include <cuda_fp16.h>
#include <math.h>
#include <stdint.h>

#define N_ROIS 2000
#define MPAD   2048
#define IN_F   12544
#define REP    1024
#define NHEAD  512
#define NCLS   91
#define NC1    90
#define NPAD   2048
#define BBOX_CLIP_F 4.135166556742356f
#define MAXDET 100

// ======================= static scratch (no allocs) =======================
__device__ float gWhf[REP * NHEAD];
__device__ float gBiasH[NHEAD];
__device__ float gH1f[MPAD * REP];
__device__ float gH2f[MPAD * REP];
__device__ float g_comb[N_ROIS * NHEAD];
__device__ float g_scores[N_ROIS * NCLS];
__device__ unsigned long long g_surv[NC1 * MAXDET];
__device__ int g_snum[NC1];

// ======================= helpers =======================
__device__ __forceinline__ uint32_t s2u(const void* p) {
    uint32_t a;
    asm("{ .reg .u64 t; cvta.to.shared.u64 t, %1; cvt.u32.u64 %0, t; }" : "=r"(a) : "l"(p));
    return a;
}
__device__ __forceinline__ void ldm4(uint32_t* r, uint32_t addr) {
    asm volatile("ldmatrix.sync.aligned.m8n8.x4.shared.b16 {%0,%1,%2,%3}, [%4];"
                 : "=r"(r[0]), "=r"(r[1]), "=r"(r[2]), "=r"(r[3]) : "r"(addr));
}
__device__ __forceinline__ void ldm4t(uint32_t* r, uint32_t addr) {
    asm volatile("ldmatrix.sync.aligned.m8n8.x4.trans.shared.b16 {%0,%1,%2,%3}, [%4];"
                 : "=r"(r[0]), "=r"(r[1]), "=r"(r[2]), "=r"(r[3]) : "r"(addr));
}
__device__ __forceinline__ void mma_f16(float* d, const uint32_t* a, const uint32_t* b) {
    asm volatile(
        "mma.sync.aligned.m16n8k16.row.col.f32.f16.f16.f32 "
        "{%0,%1,%2,%3}, {%4,%5,%6,%7}, {%8,%9}, {%0,%1,%2,%3};"
        : "+f"(d[0]), "+f"(d[1]), "+f"(d[2]), "+f"(d[3])
        : "r"(a[0]), "r"(a[1]), "r"(a[2]), "r"(a[3]), "r"(b[0]), "r"(b[1]));
}
__device__ __forceinline__ void split2u(float x, __half& h, __half& l) {
    h = __float2half_rn(x);
    l = __float2half_rn(x - __half2float(h));
}
__device__ __forceinline__ uint32_t pack2(__half a, __half b) {
    __half2 t; t.x = a; t.y = b;
    return *reinterpret_cast<uint32_t*>(&t);
}
// split 8 consecutive floats into hi uint4 / lo uint4
__device__ __forceinline__ void split8(const float4& v0, const float4& v1,
                                       uint4& hi, uint4& lo) {
    __half h0, l0, h1, l1, h2, l2, h3, l3, h4, l4, h5, l5, h6, l6, h7, l7;
    split2u(v0.x, h0, l0); split2u(v0.y, h1, l1);
    split2u(v0.z, h2, l2); split2u(v0.w, h3, l3);
    split2u(v1.x, h4, l4); split2u(v1.y, h5, l5);
    split2u(v1.z, h6, l6); split2u(v1.w, h7, l7);
    hi.x = pack2(h0, h1); hi.y = pack2(h2, h3);
    hi.z = pack2(h4, h5); hi.w = pack2(h6, h7);
    lo.x = pack2(l0, l1); lo.y = pack2(l2, l3);
    lo.z = pack2(l4, l5); lo.w = pack2(l6, l7);
}
__device__ __forceinline__ void decode_one(
    int n, int c, const float* __restrict__ P, float Wim, float Him,
    float& x1, float& y1, float& x2, float& y2)
{
    const float4 p = *reinterpret_cast<const float4*>(&P[n * 4]);
    const float pw = p.z - p.x;
    const float ph = p.w - p.y;
    const float pcx = p.x + 0.5f * pw;
    const float pcy = p.y + 0.5f * ph;
    const float4 r = *reinterpret_cast<const float4*>(&g_comb[(size_t)n * NHEAD + 92 + c * 4]);
    const float dx = r.x / 10.0f;
    const float dy = r.y / 10.0f;
    const float dw = fminf(r.z / 5.0f, BBOX_CLIP_F);
    const float dh = fminf(r.w / 5.0f, BBOX_CLIP_F);
    const float cx = dx * pw + pcx;
    const float cy = dy * ph + pcy;
    const float w = expf(dw) * pw;
    const float hh = expf(dh) * ph;
    x1 = fminf(fmaxf(cx - 0.5f * w, 0.f), Wim);
    y1 = fminf(fmaxf(cy - 0.5f * hh, 0.f), Him);
    x2 = fminf(fmaxf(cx + 0.5f * w, 0.f), Wim);
    y2 = fminf(fmaxf(cy + 0.5f * hh, 0.f), Him);
}

// ======================= tiny pre-pass =======================
__global__ void build_headW(const float* __restrict__ Wc, const float* __restrict__ Wr) {
    const int idx = blockIdx.x * 256 + threadIdx.x;
    const int k = idx >> 9;
    const int n = idx & (NHEAD - 1);
    float v = 0.f;
    if (n < NCLS) v = Wc[(size_t)k * NCLS + n];
    else if (n >= 92 && n < 92 + 4 * NCLS) v = Wr[(size_t)k * (4 * NCLS) + (n - 92)];
    gWhf[idx] = v;
}
__global__ void build_bias(const float* __restrict__ bc, const float* __restrict__ br) {
    const int c = blockIdx.x * 256 + threadIdx.x;
    if (c >= NHEAD) return;
    float v = 0.f;
    if (c < NCLS) v = bc[c];
    else if (c >= 92 && c < 92 + 4 * NCLS) v = br[c - 92];
    gBiasH[c] = v;
}

// ======================= 512-thread fused-split HMMA GEMM (BN=128) =======================
// 16 warps in 4x4 grid, warp tile 32x32. acc += Ah*Bh + Ah*Bl + Al*Bh, one fp32 acc.
#define STG512   32768
#define SMEM512  (3 * STG512)

__global__ void __launch_bounds__(512, 1) hgemm512(
    const float* __restrict__ A, const float* __restrict__ B,
    const float* __restrict__ bias, int K, int lda, int ldb,
    int Mreal, int relu, float* __restrict__ C, int ldc)
{
    extern __shared__ __align__(16) char smem[];
    const uint32_t sb = s2u(smem);
    const int tid = threadIdx.x;
    const int lane = tid & 31, wid = tid >> 5;     // 16 warps
    const int wm = wid >> 2, wn = wid & 3;         // 4x4
    const int bm = blockIdx.y * 128, bn = blockIdx.x * 128;
    const int niter = K >> 5;

    float acc[2][4][4];
#pragma unroll
    for (int m = 0; m < 2; ++m)
#pragma unroll
        for (int n = 0; n < 4; ++n)
#pragma unroll
            for (int e = 0; e < 4; ++e) acc[m][n][e] = 0.f;

    const int arow = tid >> 2, ac8 = tid & 3;
    const int brow = tid >> 4, bc8 = tid & 15;

    float4 aS0, aS1, bS0, bS1;
    auto ldgA = [&](int i) {
        const int k0 = i * 32 + ac8 * 8;
        const int gr = bm + arow;
        if (gr < Mreal) {
            const float* p = A + (size_t)gr * lda + k0;
            aS0 = *(const float4*)p;
            aS1 = *(const float4*)(p + 4);
        } else {
            aS0 = make_float4(0.f, 0.f, 0.f, 0.f);
            aS1 = aS0;
        }
    };
    auto ldgB = [&](int i) {
        const float* p = B + (size_t)(i * 32 + brow) * ldb + bn + bc8 * 8;
        bS0 = *(const float4*)p;
        bS1 = *(const float4*)(p + 4);
    };
    auto stsStage = [&](int i) {
        char* st = smem + (size_t)(i % 3) * STG512;
        uint4 hi, lo;
        // A
        split8(aS0, aS1, hi, lo);
        uint32_t relh = (uint32_t)(arow * 128 + ac8 * 16);
        relh ^= (relh >> 3) & 0x70;
        uint32_t rell = (uint32_t)(arow * 128 + 64 + ac8 * 16);
        rell ^= (rell >> 3) & 0x70;
        *(uint4*)(st + relh) = hi;
        *(uint4*)(st + rell) = lo;
        // B
        split8(bS0, bS1, hi, lo);
        uint32_t relb = (uint32_t)(brow * 256 + bc8 * 16);
        relb ^= ((relb >> 8) & 7) << 4;
        *(uint4*)(st + 16384 + relb) = hi;
        *(uint4*)(st + 16384 + 8192 + relb) = lo;
    };
    auto compute = [&](int i) {
        const uint32_t ab = sb + (uint32_t)(i % 3) * STG512;
        const uint32_t bb = ab + 16384;
#pragma unroll
        for (int kk = 0; kk < 2; ++kk) {
            uint32_t Af[2][4], Lf[2][4], Bf[4][2], Mf[4][2];
#pragma unroll
            for (int m = 0; m < 2; ++m) {
                const int row = wm * 32 + m * 16 + (lane & 15);
                const int colb = kk * 32 + ((lane >> 4) << 4);
                uint32_t rr1 = (uint32_t)(row * 128 + colb);
                uint32_t rr2 = (uint32_t)(row * 128 + 64 + colb);
                rr1 ^= (rr1 >> 3) & 0x70;
                rr2 ^= (rr2 >> 3) & 0x70;
                ldm4(Af[m], ab + rr1);
                ldm4(Lf[m], ab + rr2);
            }
#pragma unroll
            for (int p = 0; p < 2; ++p) {
                const int grp = lane >> 3, kr = lane & 7;
                const int kx = kk * 16 + (grp & 1) * 8 + kr;
                const int nb = wn * 32 + p * 16 + (grp >> 1) * 8;
                uint32_t rel = (uint32_t)(kx * 256 + nb * 2);
                rel ^= ((rel >> 8) & 7) << 4;
                uint32_t t[4];
                ldm4t(t, bb + rel);
                Bf[2 * p][0] = t[0]; Bf[2 * p][1] = t[1];
                Bf[2 * p + 1][0] = t[2]; Bf[2 * p + 1][1] = t[3];
                ldm4t(t, bb + 8192 + rel);
                Mf[2 * p][0] = t[0]; Mf[2 * p][1] = t[1];
                Mf[2 * p + 1][0] = t[2]; Mf[2 * p + 1][1] = t[3];
            }
#pragma unroll
            for (int m = 0; m < 2; ++m)
#pragma unroll
                for (int n = 0; n < 4; ++n) {
                    mma_f16(acc[m][n], Af[m], Bf[n]);
                    mma_f16(acc[m][n], Af[m], Mf[n]);
                    mma_f16(acc[m][n], Lf[m], Bf[n]);
                }
        }
    };

    ldgA(0); ldgB(0);
    stsStage(0);
    if (niter > 1) { ldgA(1); ldgB(1); }
    __syncthreads();
    for (int i = 0; i < niter; ++i) {
        if (i + 1 < niter) stsStage(i + 1);
        if (i + 2 < niter) { ldgA(i + 2); ldgB(i + 2); }
        __syncthreads();
        compute(i);
    }

    // epilogue
    const int rb = bm + wm * 32 + (lane >> 2);
    const int cb = bn + wn * 32 + 2 * (lane & 3);
#pragma unroll
    for (int m = 0; m < 2; ++m) {
#pragma unroll
        for (int n = 0; n < 4; ++n) {
            const int cc = cb + n * 8;
            const float2 bi = *(const float2*)&bias[cc];
#pragma unroll
            for (int hf = 0; hf < 2; ++hf) {
                const int r = rb + m * 16 + hf * 8;
                if (r < Mreal) {
                    float v0 = acc[m][n][2 * hf + 0] + bi.x;
                    float v1 = acc[m][n][2 * hf + 1] + bi.y;
                    if (relu) { v0 = fmaxf(v0, 0.f); v1 = fmaxf(v1, 0.f); }
                    float2 o; o.x = v0; o.y = v1;
                    *(float2*)&C[(size_t)r * ldc + cc] = o;
                }
            }
        }
    }
}

// ======================= 256-thread fused-split GEMM (BN=64, for heads) =======================
template <int BN>
__global__ void __launch_bounds__(256, 1) hgemmF(
    const float* __restrict__ A, const float* __restrict__ B,
    const float* __restrict__ bias, int K, int lda, int ldb,
    int Mreal, int relu, float* __restrict__ C, int ldc)
{
    constexpr int ROWB  = BN * 2;
    constexpr int BTILE = 32 * ROWB;
    constexpr int STG   = 16384 + 2 * BTILE;
    constexpr int BJ    = (BN == 128) ? 4 : 2;
    constexpr int NWN   = BN / 32;
    constexpr int MF    = BN / 32;

    extern __shared__ __align__(16) char smem[];
    const uint32_t sb = s2u(smem);
    const int tid = threadIdx.x;
    const int lane = tid & 31, wid = tid >> 5;
    const int wn = wid % NWN, wm = wid / NWN;
    const int wmbase = wm * (MF * 16);
    const int bm = blockIdx.y * 128, bn = blockIdx.x * BN;
    const int niter = K >> 5;

    float acc[MF][4][4];
#pragma unroll
    for (int m = 0; m < MF; ++m)
#pragma unroll
        for (int n = 0; n < 4; ++n)
#pragma unroll
            for (int e = 0; e < 4; ++e) acc[m][n][e] = 0.f;

    float4 aS[4];
    float4 bS[BJ];
    const int r0 = tid >> 3, seg = tid & 7;

    auto ldgA = [&](int i) {
        const int k0 = i * 32;
#pragma unroll
        for (int j = 0; j < 4; ++j) {
            const int gr = bm + r0 + 32 * j;
            if (gr < Mreal) aS[j] = *(const float4*)(A + (size_t)gr * lda + k0 + seg * 4);
            else aS[j] = make_float4(0.f, 0.f, 0.f, 0.f);
        }
    };
    auto ldgB = [&](int i) {
        const int k0 = i * 32;
#pragma unroll
        for (int j = 0; j < BJ; ++j) {
            const int nf = seg * 4 + j * 32;
            bS[j] = *(const float4*)(B + (size_t)(k0 + r0) * ldb + bn + nf);
        }
    };
    auto stsStage = [&](int i) {
        char* st = smem + (size_t)(i % 3) * STG;
#pragma unroll
        for (int j = 0; j < 4; ++j) {
            const int row = r0 + 32 * j;
            __half h0, l0, h1, l1, h2, l2, h3, l3;
            split2u(aS[j].x, h0, l0); split2u(aS[j].y, h1, l1);
            split2u(aS[j].z, h2, l2); split2u(aS[j].w, h3, l3);
            uint32_t relh = (uint32_t)(row * 128 + seg * 8);
            relh ^= (relh >> 3) & 0x70;
            uint32_t rell = (uint32_t)(row * 128 + 64 + seg * 8);
            rell ^= (rell >> 3) & 0x70;
            uint2 vh; vh.x = pack2(h0, h1); vh.y = pack2(h2, h3);
            uint2 vl; vl.x = pack2(l0, l1); vl.y = pack2(l2, l3);
            *(uint2*)(st + relh) = vh;
            *(uint2*)(st + rell) = vl;
        }
#pragma unroll
        for (int j = 0; j < BJ; ++j) {
            const int nf = seg * 4 + j * 32;
            __half h0, l0, h1, l1, h2, l2, h3, l3;
            split2u(bS[j].x, h0, l0); split2u(bS[j].y, h1, l1);
            split2u(bS[j].z, h2, l2); split2u(bS[j].w, h3, l3);
            uint32_t rel = (uint32_t)(r0 * ROWB + nf * 2);
            if (BN == 128) rel ^= ((rel >> 8) & 7) << 4;
            else           rel ^= ((rel >> 7) & 7) << 4;
            uint2 vh; vh.x = pack2(h0, h1); vh.y = pack2(h2, h3);
            uint2 vl; vl.x = pack2(l0, l1); vl.y = pack2(l2, l3);
            *(uint2*)(st + 16384 + rel) = vh;
            *(uint2*)(st + 16384 + BTILE + rel) = vl;
        }
    };
    auto compute = [&](int i) {
        const uint32_t ab = sb + (uint32_t)(i % 3) * STG;
        const uint32_t bb = ab + 16384;
#pragma unroll
        for (int kk = 0; kk < 2; ++kk) {
            uint32_t Af[MF][4], Lf[MF][4], Bf[4][2], Mf[4][2];
#pragma unroll
            for (int m = 0; m < MF; ++m) {
                const int row = wmbase + m * 16 + (lane & 15);
                const int colb = kk * 32 + ((lane >> 4) << 4);
                uint32_t rr1 = (uint32_t)(row * 128 + colb);
                uint32_t rr2 = (uint32_t)(row * 128 + 64 + colb);
                rr1 ^= (rr1 >> 3) & 0x70;
                rr2 ^= (rr2 >> 3) & 0x70;
                ldm4(Af[m], ab + rr1);
                ldm4(Lf[m], ab + rr2);
            }
#pragma unroll
            for (int p = 0; p < 2; ++p) {
                const int grp = lane >> 3, kr = lane & 7;
                const int kx = kk * 16 + (grp & 1) * 8 + kr;
                const int nb = wn * 32 + p * 16 + (grp >> 1) * 8;
                uint32_t rel = (uint32_t)(kx * ROWB + nb * 2);
                if (BN == 128) rel ^= ((rel >> 8) & 7) << 4;
                else           rel ^= ((rel >> 7) & 7) << 4;
                uint32_t t[4];
                ldm4t(t, bb + rel);
                Bf[2 * p][0] = t[0]; Bf[2 * p][1] = t[1];
                Bf[2 * p + 1][0] = t[2]; Bf[2 * p + 1][1] = t[3];
                ldm4t(t, bb + BTILE + rel);
                Mf[2 * p][0] = t[0]; Mf[2 * p][1] = t[1];
                Mf[2 * p + 1][0] = t[2]; Mf[2 * p + 1][1] = t[3];
            }
#pragma unroll
            for (int m = 0; m < MF; ++m)
#pragma unroll
                for (int n = 0; n < 4; ++n) {
                    mma_f16(acc[m][n], Af[m], Bf[n]);
                    mma_f16(acc[m][n], Af[m], Mf[n]);
                    mma_f16(acc[m][n], Lf[m], Bf[n]);
                }
        }
    };

    ldgA(0); ldgB(0);
    stsStage(0);
    if (niter > 1) { ldgA(1); ldgB(1); }
    __syncthreads();
    for (int i = 0; i < niter; ++i) {
        if (i + 1 < niter) stsStage(i + 1);
        if (i + 2 < niter) { ldgA(i + 2); ldgB(i + 2); }
        __syncthreads();
        compute(i);
    }

    const int rb = bm + wmbase + (lane >> 2);
    const int cb = bn + wn * 32 + 2 * (lane & 3);
#pragma unroll
    for (int m = 0; m < MF; ++m) {
#pragma unroll
        for (int n = 0; n < 4; ++n) {
            const int cc = cb + n * 8;
            const float2 bi = *(const float2*)&bias[cc];
#pragma unroll
            for (int hf = 0; hf < 2; ++hf) {
                const int r = rb + m * 16 + hf * 8;
                if (r < Mreal) {
                    float v0 = acc[m][n][2 * hf + 0] + bi.x;
                    float v1 = acc[m][n][2 * hf + 1] + bi.y;
                    if (relu) { v0 = fmaxf(v0, 0.f); v1 = fmaxf(v1, 0.f); }
                    float2 o; o.x = v0; o.y = v1;
                    *(float2*)&C[(size_t)r * ldc + cc] = o;
                }
            }
        }
    }
}

// ======================= softmax =======================
__global__ void softmax_kernel() {
    const int n = blockIdx.x;
    const int lane = threadIdx.x;
    float v[3];
    float mx = -3.4e38f;
#pragma unroll
    for (int t = 0; t < 3; ++t) {
        const int i = lane + 32 * t;
        v[t] = (i < NCLS) ? g_comb[(size_t)n * NHEAD + i] : -3.4e38f;
        mx = fmaxf(mx, v[t]);
    }
#pragma unroll
    for (int s = 16; s > 0; s >>= 1) mx = fmaxf(mx, __shfl_xor_sync(0xffffffffu, mx, s));
    float sum = 0.f;
#pragma unroll
    for (int t = 0; t < 3; ++t) {
        const int i = lane + 32 * t;
        if (i < NCLS) { v[t] = expf(v[t] - mx); sum += v[t]; }
    }
#pragma unroll
    for (int s = 16; s > 0; s >>= 1) sum += __shfl_xor_sync(0xffffffffu, sum, s);
#pragma unroll
    for (int t = 0; t < 3; ++t) {
        const int i = lane + 32 * t;
        if (i < NCLS) g_scores[n * NCLS + i] = v[t] / sum;
    }
}

// ======================= per-class NMS =======================
#define CSMEM (4 * NPAD * 4 + NPAD * 8 + NPAD)

__global__ void __launch_bounds__(256) class_nms(
    const float* __restrict__ P, const int* __restrict__ imh, const int* __restrict__ imw)
{
    extern __shared__ __align__(16) char smemraw[];
    float* sx1 = (float*)smemraw;
    float* sy1 = sx1 + NPAD;
    float* sx2 = sy1 + NPAD;
    float* sy2 = sx2 + NPAD;
    unsigned long long* keys = (unsigned long long*)(sy2 + NPAD);
    char* alive = (char*)(keys + NPAD);
    __shared__ int s_nsurv;

    const int tid = threadIdx.x;
    const int cls = blockIdx.x;
    const int c = cls + 1;
    const float Wim = (float)(*imw);
    const float Him = (float)(*imh);
    const float offv = (float)c * (fmaxf(Wim, Him) + 1.0f);

    if (tid == 0) s_nsurv = 0;

    for (int n = tid; n < NPAD; n += 256) {
        unsigned long long key = 0ull;
        if (n < N_ROIS) {
            float x1, y1, x2, y2;
            decode_one(n, c, P, Wim, Him, x1, y1, x2, y2);
            const float s = g_scores[n * NCLS + c];
            if (s > 0.05f && (x2 - x1) >= 0.01f && (y2 - y1) >= 0.01f) {
                sx1[n] = x1 + offv;
                sy1[n] = y1 + offv;
                sx2[n] = x2 + offv;
                sy2[n] = y2 + offv;
                key = ((unsigned long long)__float_as_uint(s) << 32)
                    | (unsigned long long)(0xFFFFFFFFu - (unsigned)n);
            }
        }
        keys[n] = key;
        alive[n] = 1;
    }
    __syncthreads();

    for (int k = 2; k <= NPAD; k <<= 1) {
        for (int j = k >> 1; j > 0; j >>= 1) {
            for (int i = tid; i < NPAD; i += 256) {
                const int l = i ^ j;
                if (l > i) {
                    const unsigned long long a = keys[i], b = keys[l];
                    const bool up = ((i & k) == 0);
                    if (up ? (a < b) : (a > b)) { keys[i] = b; keys[l] = a; }
                }
            }
            __syncthreads();
        }
    }

    for (int pos = 0; pos < NPAD; ++pos) {
        const unsigned long long k = keys[pos];
        if (k == 0ull) break;
        if (!alive[pos]) continue;
        if (s_nsurv >= MAXDET) break;
        const int ni = (int)(0xFFFFFFFFu - (unsigned)(k & 0xFFFFFFFFull));
        const float bx1 = sx1[ni], by1 = sy1[ni], bx2 = sx2[ni], by2 = sy2[ni];
        const float ai = (bx2 - bx1) * (by2 - by1);
        if (tid == 0) {
            const unsigned flat = (unsigned)(ni * NC1 + cls);
            g_surv[cls * MAXDET + s_nsurv] =
                (k & 0xFFFFFFFF00000000ull) | (unsigned long long)(0xFFFFFFFFu - flat);
            s_nsurv++;
        }
        for (int j = pos + 1 + tid; j < NPAD; j += 256) {
            if (!alive[j]) continue;
            const unsigned long long k2 = keys[j];
            if (k2 == 0ull) continue;
            const int nj = (int)(0xFFFFFFFFu - (unsigned)(k2 & 0xFFFFFFFFull));
            const float xx1 = fmaxf(bx1, sx1[nj]);
            const float yy1 = fmaxf(by1, sy1[nj]);
            const float xx2 = fminf(bx2, sx2[nj]);
            const float yy2 = fminf(by2, sy2[nj]);
            const float inter = fmaxf(xx2 - xx1, 0.f) * fmaxf(yy2 - yy1, 0.f);
            const float aj = (sx2[nj] - sx1[nj]) * (sy2[nj] - sy1[nj]);
            const float iou = inter / (ai + aj - inter + 1e-9f);
            if (iou > 0.5f) alive[j] = 0;
        }
        __syncthreads();
    }
    __syncthreads();
    if (tid == 0) g_snum[cls] = s_nsurv;
}

// ======================= merge + output =======================
__global__ void __launch_bounds__(128) final_select(
    const float* __restrict__ P, const int* __restrict__ imh, const int* __restrict__ imw,
    float* __restrict__ out, int out_size)
{
    __shared__ unsigned long long red[128];
    __shared__ int heads[NC1];
    __shared__ int cnts[NC1];
    __shared__ int keep[MAXDET];
    __shared__ int s_w;

    const int tid = threadIdx.x;
    if (tid < NC1) { heads[tid] = 0; cnts[tid] = g_snum[tid]; }
    if (tid < MAXDET) keep[tid] = -1;
    __syncthreads();

    for (int it = 0; it < MAXDET; ++it) {
        unsigned long long cand = 0ull;
        if (tid < NC1 && heads[tid] < cnts[tid])
            cand = g_surv[tid * MAXDET + heads[tid]];
        red[tid] = cand;
        __syncthreads();
        for (int s = 64; s > 0; s >>= 1) {
            if (tid < s) { if (red[tid + s] > red[tid]) red[tid] = red[tid + s]; }
            __syncthreads();
        }
        const unsigned long long best = red[0];
        if (best == 0ull) break;
        if (tid < NC1 && cand == best) s_w = tid;
        __syncthreads();
        if (tid == 0) {
            heads[s_w]++;
            keep[it] = (int)(0xFFFFFFFFu - (unsigned)(best & 0xFFFFFFFFull));
        }
        __syncthreads();
    }

    if (tid < MAXDET) {
        const int k = keep[tid];
        float b0 = 0, b1 = 0, b2 = 0, b3 = 0, s = 0, l = 0;
        if (k >= 0) {
            const int n = k / NC1;
            const int c = k % NC1 + 1;
            const float Wim = (float)(*imw);
            const float Him = (float)(*imh);
            float x1, y1, x2, y2;
            decode_one(n, c, P, Wim, Him, x1, y1, x2, y2);
            b0 = x1; b1 = y1; b2 = x2; b3 = y2;
            s = g_scores[n * NCLS + c];
            l = (float)c;
        }
        if (tid * 4 + 3 < out_size) {
            out[tid * 4 + 0] = b0;
            out[tid * 4 + 1] = b1;
            out[tid * 4 + 2] = b2;
            out[tid * 4 + 3] = b3;
        }
        if (4 * MAXDET + tid < out_size) out[4 * MAXDET + tid] = s;
        if (5 * MAXDET + tid < out_size) out[5 * MAXDET + tid] = l;
    }
}

// ======================= launch =======================
extern "C" void kernel_launch(void* const* d_in, const int* in_sizes, int n_in,
                              void* d_out, int out_size) {
    const float* X  = (const float*)d_in[0];
    const float* P  = (const float*)d_in[1];
    const float* W1 = (const float*)d_in[2];
    const float* b1 = (const float*)d_in[3];
    const float* W2 = (const float*)d_in[4];
    const float* b2 = (const float*)d_in[5];
    const float* Wc = (const float*)d_in[6];
    const float* bc = (const float*)d_in[7];
    const float* Wr = (const float*)d_in[8];
    const float* br = (const float*)d_in[9];
    const int* imh  = (const int*)d_in[10];
    const int* imw  = (const int*)d_in[11];

    float *pWh, *pBiasH, *pH1, *pH2, *pComb;
    cudaGetSymbolAddress((void**)&pWh, gWhf);
    cudaGetSymbolAddress((void**)&pBiasH, gBiasH);
    cudaGetSymbolAddress((void**)&pH1, gH1f);
    cudaGetSymbolAddress((void**)&pH2, gH2f);
    cudaGetSymbolAddress((void**)&pComb, g_comb);

    const int SMEM64 = 3 * (16384 + 2 * (32 * 128));   // 73728
    cudaFuncSetAttribute(hgemm512, cudaFuncAttributeMaxDynamicSharedMemorySize, SMEM512);
    cudaFuncSetAttribute(hgemmF<64>, cudaFuncAttributeMaxDynamicSharedMemorySize, SMEM64);
    cudaFuncSetAttribute(class_nms, cudaFuncAttributeMaxDynamicSharedMemorySize, CSMEM);

    build_headW<<<REP * NHEAD / 256, 256>>>(Wc, Wr);
    build_bias<<<(NHEAD + 255) / 256, 256>>>(bc, br);

    // GEMM1: h1 = relu(X @ W1 + b1)
    hgemm512<<<dim3(REP / 128, MPAD / 128), 512, SMEM512>>>(
        X, W1, b1, IN_F, IN_F, REP, N_ROIS, 1, pH1, REP);
    // GEMM2: h2 = relu(h1 @ W2 + b2)
    hgemm512<<<dim3(REP / 128, MPAD / 128), 512, SMEM512>>>(
        pH1, W2, b2, REP, REP, REP, N_ROIS, 1, pH2, REP);
    // heads: comb = h2 @ Wh + biasH  (BN=64 -> 128 CTAs)
    hgemmF<64><<<dim3(NHEAD / 64, MPAD / 128), 256, SMEM64>>>(
        pH2, pWh, pBiasH, REP, REP, NHEAD, N_ROIS, 0, pComb, NHEAD);

    softmax_kernel<<<N_ROIS, 32>>>();
    class_nms<<<NC1, 256, CSMEM>>>(P, imh, imw);
    final_select<<<1, 128>>>(P, imh, imw, (float*)d_out, out_size);
}